// round 1
// baseline (speedup 1.0000x reference)
#include <cuda_runtime.h>
#include <math.h>

#define BATCH 4
#define SEQ   512
#define EMB   256
#define NH    8
#define HD    32
#define NC    10
#define NBUCK 32

// ---------------- scratch (device globals; no allocation) ----------------
__device__ float g_W1c[NC*NH*HD*HD];          // combined W1_ [C][h][m][n]
__device__ float g_W2c[NC*NH*HD*HD];          // combined W2_ [C][h][n][m] (stored as built: [C][h][x][y], ctx contracts x)
__device__ float g_q [BATCH*NH*SEQ*HD];       // [b][h][l][d]
__device__ float g_k [BATCH*NH*SEQ*HD];
__device__ float g_v [BATCH*NH*SEQ*HD];
__device__ float g_qA[BATCH*NH*SEQ*4*HD];     // [b][h][q][tk][n]
__device__ float g_u [BATCH*NH*SEQ*4*HD];     // [b][h][k][tq][m]
__device__ float g_sc[BATCH*NH*SEQ*SEQ];      // scores -> probs (in place)
__device__ float g_ctx[BATCH*SEQ*EMB];        // [b][l][h*32+m]
__device__ unsigned char g_bucket[SEQ*SEQ];   // T5 bucket[q][k]

__device__ __forceinline__ int cmap(int tq, int tk){
    return (tq==0 || tk==0) ? 0 : (tq-1)*3 + tk;
}

// ---------------- K1: softmax(alpha) + combined W1_/W2_ ----------------
__global__ void k_prep(const float* __restrict__ W1, const float* __restrict__ a1,
                       const float* __restrict__ W2, const float* __restrict__ a2){
    __shared__ float sa1[NC*3*NH];
    __shared__ float sa2[NC*3*NH];
    int tid = threadIdx.x;
    if (tid < NC*NH){
        int Ci = tid / NH, h = tid % NH;
        {
            float v0=a1[(Ci*3+0)*NH+h], v1=a1[(Ci*3+1)*NH+h], v2=a1[(Ci*3+2)*NH+h];
            float mx=fmaxf(v0,fmaxf(v1,v2));
            float e0=expf(v0-mx), e1=expf(v1-mx), e2=expf(v2-mx);
            float inv=1.0f/(e0+e1+e2);
            sa1[(Ci*3+0)*NH+h]=e0*inv; sa1[(Ci*3+1)*NH+h]=e1*inv; sa1[(Ci*3+2)*NH+h]=e2*inv;
        }
        {
            float v0=a2[(Ci*3+0)*NH+h], v1=a2[(Ci*3+1)*NH+h], v2=a2[(Ci*3+2)*NH+h];
            float mx=fmaxf(v0,fmaxf(v1,v2));
            float e0=expf(v0-mx), e1=expf(v1-mx), e2=expf(v2-mx);
            float inv=1.0f/(e0+e1+e2);
            sa2[(Ci*3+0)*NH+h]=e0*inv; sa2[(Ci*3+1)*NH+h]=e1*inv; sa2[(Ci*3+2)*NH+h]=e2*inv;
        }
    }
    __syncthreads();
    for (int idx=tid; idx<NC*NH*HD*HD; idx+=blockDim.x){
        int n = idx & 31, m = (idx>>5)&31, h=(idx>>10)&7, Ci = idx>>13;
        float acc1=0.f, acc2=0.f;
        #pragma unroll
        for (int b=0;b<3;b++){
            acc1 += W1[((b*NH+h)*HD+m)*HD+n] * sa1[(Ci*3+b)*NH+h];
            acc2 += W2[((b*NH+h)*HD+m)*HD+n] * sa2[(Ci*3+b)*NH+h];
        }
        g_W1c[idx]=acc1; g_W2c[idx]=acc2;
    }
}

// ---------------- K2: T5 relative-position buckets ----------------
__global__ void k_bucket(){
    int idx = blockIdx.x*blockDim.x + threadIdx.x;
    if (idx >= SEQ*SEQ) return;
    int q = idx >> 9, k = idx & (SEQ-1);
    int n = q - k;                       // n = -(k-q)
    int ret = (n < 0) ? 16 : 0;
    int na = n < 0 ? -n : n;
    int bkt;
    if (na < 8) bkt = na;
    else {
        int v = (int)(log((double)na / 8.0) / log(5.0) * 8.0);
        if (v > 7) v = 7;
        bkt = 8 + v;
    }
    g_bucket[idx] = (unsigned char)(ret + bkt);
}

// ---------------- K3: QKV projection (warp per token) ----------------
__global__ void __launch_bounds__(512) k_qkv(const float* __restrict__ x, const int* __restrict__ ts,
                      const float* __restrict__ Wq, const float* __restrict__ Wk,
                      const float* __restrict__ Wv){
    __shared__ float sx[16*EMB];
    int tid=threadIdx.x, w=tid>>5, lane=tid&31;
    int token0 = blockIdx.x*16;
    const float4* xg = (const float4*)(x + token0*EMB);
    float4* s4 = (float4*)sx;
    for (int i=tid;i<16*EMB/4;i+=512) s4[i]=xg[i];
    __syncthreads();
    int token = token0 + w;
    int t = ts[token];
    int o = lane*8;
    const float* wq = Wq + t*EMB*EMB + o;
    const float* wk = Wk + t*EMB*EMB + o;
    const float* wv = Wv + t*EMB*EMB + o;
    float aq0=0,aq1=0,aq2=0,aq3=0,aq4=0,aq5=0,aq6=0,aq7=0;
    float ak0=0,ak1=0,ak2=0,ak3=0,ak4=0,ak5=0,ak6=0,ak7=0;
    float av0=0,av1=0,av2=0,av3=0,av4=0,av5=0,av6=0,av7=0;
    const float* xr = sx + w*EMB;
    #pragma unroll 4
    for (int i=0;i<EMB;i++){
        float xi = xr[i];
        float4 a = *(const float4*)(wq + i*EMB);
        float4 b = *(const float4*)(wq + i*EMB + 4);
        aq0+=xi*a.x; aq1+=xi*a.y; aq2+=xi*a.z; aq3+=xi*a.w;
        aq4+=xi*b.x; aq5+=xi*b.y; aq6+=xi*b.z; aq7+=xi*b.w;
        float4 c = *(const float4*)(wk + i*EMB);
        float4 d = *(const float4*)(wk + i*EMB + 4);
        ak0+=xi*c.x; ak1+=xi*c.y; ak2+=xi*c.z; ak3+=xi*c.w;
        ak4+=xi*d.x; ak5+=xi*d.y; ak6+=xi*d.z; ak7+=xi*d.w;
        float4 e = *(const float4*)(wv + i*EMB);
        float4 f = *(const float4*)(wv + i*EMB + 4);
        av0+=xi*e.x; av1+=xi*e.y; av2+=xi*e.z; av3+=xi*e.w;
        av4+=xi*f.x; av5+=xi*f.y; av6+=xi*f.z; av7+=xi*f.w;
    }
    int bb = token>>9, l = token&(SEQ-1);
    int h = o>>5, dd = o&31;
    int base = ((bb*NH+h)*SEQ+l)*HD + dd;
    *(float4*)&g_q[base]   = make_float4(aq0,aq1,aq2,aq3);
    *(float4*)&g_q[base+4] = make_float4(aq4,aq5,aq6,aq7);
    *(float4*)&g_k[base]   = make_float4(ak0,ak1,ak2,ak3);
    *(float4*)&g_k[base+4] = make_float4(ak4,ak5,ak6,ak7);
    *(float4*)&g_v[base]   = make_float4(av0,av1,av2,av3);
    *(float4*)&g_v[base+4] = make_float4(av4,av5,av6,av7);
}

// ---------------- K4: qA / u 4-slice precompute ----------------
__global__ void __launch_bounds__(256) k_qau(const int* __restrict__ ts){
    int bh = blockIdx.x >> 2;
    int qt = blockIdx.x & 3;
    int b = bh >> 3, h = bh & 7;
    int lane32 = threadIdx.x & 31;     // n (qA) / m (u)
    int tki    = (threadIdx.x >> 5) & 3;
    int qo     = threadIdx.x >> 7;     // 0..1
    for (int qi = qo; qi < 128; qi += 2){
        int q = qt*128 + qi;
        int tok_t = ts[b*SEQ + q];
        // qA[b][h][q][tki][n] = sum_m q[m] * W1c[cmap(tok_t, tki)][h][m][n]
        {
            int c = cmap(tok_t, tki);
            const float* wb = g_W1c + (c*NH+h)*HD*HD + lane32;
            const float* qv = g_q + (bh*SEQ+q)*HD;
            float a0=0,a1=0,a2=0,a3=0;
            #pragma unroll
            for (int m=0;m<HD;m+=4){
                a0 += qv[m  ]*wb[(m  )*HD];
                a1 += qv[m+1]*wb[(m+1)*HD];
                a2 += qv[m+2]*wb[(m+2)*HD];
                a3 += qv[m+3]*wb[(m+3)*HD];
            }
            g_qA[((bh*SEQ+q)*4 + tki)*HD + lane32] = (a0+a1)+(a2+a3);
        }
        // u[b][h][k][tki(=tq)][m] = sum_n v[n] * W2c[cmap(tki, tok_t)][h][n][m]
        {
            int c = cmap(tki, tok_t);
            const float* wb = g_W2c + (c*NH+h)*HD*HD + lane32;
            const float* vv = g_v + (bh*SEQ+q)*HD;
            float a0=0,a1=0,a2=0,a3=0;
            #pragma unroll
            for (int n=0;n<HD;n+=4){
                a0 += vv[n  ]*wb[(n  )*HD];
                a1 += vv[n+1]*wb[(n+1)*HD];
                a2 += vv[n+2]*wb[(n+2)*HD];
                a3 += vv[n+3]*wb[(n+3)*HD];
            }
            g_u[((bh*SEQ+q)*4 + tki)*HD + lane32] = (a0+a1)+(a2+a3);
        }
    }
}

// ---------------- K5: scores = qA(tk)·k * scale + bias + mask ----------------
__global__ void __launch_bounds__(256) k_scores(const float* __restrict__ mask,
                                                const int* __restrict__ ts,
                                                const float* __restrict__ rp){
    int bh = blockIdx.y; int b = bh>>3, h = bh&7;
    int q0 = blockIdx.x * 32;
    __shared__ float s_qA[32*4*HD];     // 16 KB
    __shared__ float s_rp[NC*NBUCK];
    __shared__ int   s_tq[32];
    int tid = threadIdx.x;
    {
        const float4* src = (const float4*)(g_qA + (bh*SEQ+q0)*4*HD);
        float4* dst = (float4*)s_qA;
        for (int i=tid;i<32*4*HD/4;i+=256) dst[i]=src[i];
    }
    for (int i=tid;i<NC*NBUCK;i+=256) s_rp[i] = rp[i*NH + h];
    if (tid<32) s_tq[tid] = ts[b*SEQ + q0 + tid];
    __syncthreads();
    const float scale = 0.17677669529663687f; // 1/sqrt(32)
    for (int kk = tid; kk < SEQ; kk += 256){
        int tkk = ts[b*SEQ+kk];
        float kv[HD];
        const float4* kg = (const float4*)(g_k + (bh*SEQ+kk)*HD);
        #pragma unroll
        for (int j=0;j<8;j++){ float4 t4=kg[j]; kv[4*j]=t4.x; kv[4*j+1]=t4.y; kv[4*j+2]=t4.z; kv[4*j+3]=t4.w; }
        const float* mrow = mask + (size_t)b*SEQ*SEQ + kk;
        const unsigned char* brow = g_bucket + kk;
        float* orow = g_sc + ((size_t)(bh*SEQ+q0))*SEQ + kk;
        for (int qi=0; qi<32; qi++){
            const float* qa = s_qA + (qi*4 + tkk)*HD;
            float a0=0,a1=0,a2=0,a3=0;
            #pragma unroll
            for (int j=0;j<HD;j+=4){
                a0 += qa[j  ]*kv[j  ];
                a1 += qa[j+1]*kv[j+1];
                a2 += qa[j+2]*kv[j+2];
                a3 += qa[j+3]*kv[j+3];
            }
            int q = q0 + qi;
            int c = cmap(s_tq[qi], tkk);
            float bias = s_rp[c*NBUCK + brow[q*SEQ]];
            orow[(size_t)qi*SEQ] = ((a0+a1)+(a2+a3))*scale + bias + mrow[(size_t)q*SEQ];
        }
    }
}

// ---------------- K6: row softmax (in place) ----------------
__global__ void __launch_bounds__(256) k_softmax(){
    int row = blockIdx.x;
    float* p = g_sc + (size_t)row*SEQ;
    int tid = threadIdx.x;
    float v0 = p[tid], v1 = p[tid+256];
    float m = fmaxf(v0,v1);
    #pragma unroll
    for (int o=16;o;o>>=1) m = fmaxf(m, __shfl_xor_sync(0xffffffffu,m,o));
    __shared__ float sm[8];
    if ((tid&31)==0) sm[tid>>5]=m;
    __syncthreads();
    float mm = sm[0];
    #pragma unroll
    for (int i=1;i<8;i++) mm = fmaxf(mm, sm[i]);
    float e0 = __expf(v0-mm), e1 = __expf(v1-mm);
    float s = e0+e1;
    #pragma unroll
    for (int o=16;o;o>>=1) s += __shfl_xor_sync(0xffffffffu,s,o);
    __shared__ float ssum[8];
    if ((tid&31)==0) ssum[tid>>5]=s;
    __syncthreads();
    float tot = 0.f;
    #pragma unroll
    for (int i=0;i<8;i++) tot += ssum[i];
    float inv = 1.0f/tot;
    p[tid]     = e0*inv;
    p[tid+256] = e1*inv;
}

// ---------------- K7: ctx = probs @ u[:, tq(q), :] ----------------
__global__ void __launch_bounds__(256) k_ctx(const int* __restrict__ ts){
    int bh = blockIdx.y, b = bh>>3, h = bh&7;
    int q0 = blockIdx.x*32;
    __shared__ float s_p[32][65];     // padded
    __shared__ float s_u[64*4*HD];    // 32 KB
    __shared__ int   s_tq[32];
    int tid=threadIdx.x;
    if (tid<32) s_tq[tid]=ts[b*SEQ+q0+tid];
    int qi = tid>>3, g = tid&7;
    float ax=0,ay=0,az=0,aw=0;
    for (int kt=0; kt<8; kt++){
        __syncthreads();
        for (int i=tid;i<2048;i+=256){
            int qq=i>>6, kk=i&63;
            s_p[qq][kk] = g_sc[((size_t)(bh*SEQ+q0+qq))*SEQ + kt*64 + kk];
        }
        {
            const float4* src = (const float4*)(g_u + (size_t)(bh*SEQ + kt*64)*4*HD);
            float4* dst = (float4*)s_u;
            for (int i=tid;i<64*4*HD/4;i+=256) dst[i]=src[i];
        }
        __syncthreads();
        int tq = s_tq[qi];
        #pragma unroll 4
        for (int kk=0;kk<64;kk++){
            float pp = s_p[qi][kk];
            float4 uu = *(const float4*)(s_u + (kk*4+tq)*HD + g*4);
            ax += pp*uu.x; ay += pp*uu.y; az += pp*uu.z; aw += pp*uu.w;
        }
    }
    int q = q0+qi;
    *(float4*)&g_ctx[((size_t)(b*SEQ+q))*EMB + h*HD + g*4] = make_float4(ax,ay,az,aw);
}

// ---------------- K8: residual + LayerNorm ----------------
__global__ void __launch_bounds__(256) k_ln(const float* __restrict__ x,
                                            const float* __restrict__ gamma,
                                            const float* __restrict__ beta,
                                            float* __restrict__ out){
    int tok = blockIdx.x;
    int tid = threadIdx.x;
    float xv = g_ctx[(size_t)tok*EMB+tid] + x[(size_t)tok*EMB+tid];
    float s = xv;
    #pragma unroll
    for (int o=16;o;o>>=1) s += __shfl_xor_sync(0xffffffffu,s,o);
    __shared__ float r1[8];
    if ((tid&31)==0) r1[tid>>5]=s;
    __syncthreads();
    float tot=0.f;
    #pragma unroll
    for (int i=0;i<8;i++) tot += r1[i];
    float mu = tot*(1.0f/EMB);
    float d = xv - mu;
    float s2 = d*d;
    #pragma unroll
    for (int o=16;o;o>>=1) s2 += __shfl_xor_sync(0xffffffffu,s2,o);
    __shared__ float r2[8];
    if ((tid&31)==0) r2[tid>>5]=s2;
    __syncthreads();
    float tot2=0.f;
    #pragma unroll
    for (int i=0;i<8;i++) tot2 += r2[i];
    float var = tot2*(1.0f/EMB);
    out[(size_t)tok*EMB+tid] = d * rsqrtf(var + 1e-12f) * gamma[tid] + beta[tid];
}

// ---------------- launch ----------------
extern "C" void kernel_launch(void* const* d_in, const int* in_sizes, int n_in,
                              void* d_out, int out_size){
    const float* x    = (const float*)d_in[0];
    const float* mask = (const float*)d_in[1];
    const int*   ts   = (const int*)  d_in[2];
    const float* Wq   = (const float*)d_in[3];
    const float* Wk   = (const float*)d_in[4];
    const float* Wv   = (const float*)d_in[5];
    const float* W1   = (const float*)d_in[6];
    const float* a1   = (const float*)d_in[7];
    const float* W2   = (const float*)d_in[8];
    const float* a2   = (const float*)d_in[9];
    const float* rp   = (const float*)d_in[10];
    const float* gam  = (const float*)d_in[11];
    const float* bet  = (const float*)d_in[12];
    float* out = (float*)d_out;

    k_prep   <<<1, 256>>>(W1, a1, W2, a2);
    k_bucket <<<(SEQ*SEQ+255)/256, 256>>>();
    k_qkv    <<<BATCH*SEQ/16, 512>>>(x, ts, Wq, Wk, Wv);
    k_qau    <<<BATCH*NH*4, 256>>>(ts);
    k_scores <<<dim3(SEQ/32, BATCH*NH), 256>>>(mask, ts, rp);
    k_softmax<<<BATCH*NH*SEQ, 256>>>();
    k_ctx    <<<dim3(SEQ/32, BATCH*NH), 256>>>(ts);
    k_ln     <<<BATCH*SEQ, 256>>>(x, gam, bet, out);
}

// round 2
// speedup vs baseline: 1.0013x; 1.0013x over previous
#include <cuda_runtime.h>
#include <math.h>

#define BATCH 4
#define SEQ   512
#define EMB   256
#define NH    8
#define HD    32
#define NC    10
#define NBUCK 32

// ---------------- scratch (device globals; no allocation) ----------------
__device__ float g_W1c[NC*NH*HD*HD];          // combined W1_ [C][h][m][n]
__device__ float g_W2c[NC*NH*HD*HD];          // combined W2_ [C][h][n][m] (stored as built: [C][h][x][y], ctx contracts x)
__device__ float g_q [BATCH*NH*SEQ*HD];       // [b][h][l][d]
__device__ float g_k [BATCH*NH*SEQ*HD];
__device__ float g_v [BATCH*NH*SEQ*HD];
__device__ float g_qA[BATCH*NH*SEQ*4*HD];     // [b][h][q][tk][n]
__device__ float g_u [BATCH*NH*SEQ*4*HD];     // [b][h][k][tq][m]
__device__ float g_sc[BATCH*NH*SEQ*SEQ];      // scores -> probs (in place)
__device__ float g_ctx[BATCH*SEQ*EMB];        // [b][l][h*32+m]
__device__ unsigned char g_bucket[SEQ*SEQ];   // T5 bucket[q][k]

__device__ __forceinline__ int cmap(int tq, int tk){
    return (tq==0 || tk==0) ? 0 : (tq-1)*3 + tk;
}

// ---------------- K1: softmax(alpha) + combined W1_/W2_ ----------------
__global__ void k_prep(const float* __restrict__ W1, const float* __restrict__ a1,
                       const float* __restrict__ W2, const float* __restrict__ a2){
    __shared__ float sa1[NC*3*NH];
    __shared__ float sa2[NC*3*NH];
    int tid = threadIdx.x;
    if (tid < NC*NH){
        int Ci = tid / NH, h = tid % NH;
        {
            float v0=a1[(Ci*3+0)*NH+h], v1=a1[(Ci*3+1)*NH+h], v2=a1[(Ci*3+2)*NH+h];
            float mx=fmaxf(v0,fmaxf(v1,v2));
            float e0=expf(v0-mx), e1=expf(v1-mx), e2=expf(v2-mx);
            float inv=1.0f/(e0+e1+e2);
            sa1[(Ci*3+0)*NH+h]=e0*inv; sa1[(Ci*3+1)*NH+h]=e1*inv; sa1[(Ci*3+2)*NH+h]=e2*inv;
        }
        {
            float v0=a2[(Ci*3+0)*NH+h], v1=a2[(Ci*3+1)*NH+h], v2=a2[(Ci*3+2)*NH+h];
            float mx=fmaxf(v0,fmaxf(v1,v2));
            float e0=expf(v0-mx), e1=expf(v1-mx), e2=expf(v2-mx);
            float inv=1.0f/(e0+e1+e2);
            sa2[(Ci*3+0)*NH+h]=e0*inv; sa2[(Ci*3+1)*NH+h]=e1*inv; sa2[(Ci*3+2)*NH+h]=e2*inv;
        }
    }
    __syncthreads();
    for (int idx=tid; idx<NC*NH*HD*HD; idx+=blockDim.x){
        int n = idx & 31, m = (idx>>5)&31, h=(idx>>10)&7, Ci = idx>>13;
        float acc1=0.f, acc2=0.f;
        #pragma unroll
        for (int b=0;b<3;b++){
            acc1 += W1[((b*NH+h)*HD+m)*HD+n] * sa1[(Ci*3+b)*NH+h];
            acc2 += W2[((b*NH+h)*HD+m)*HD+n] * sa2[(Ci*3+b)*NH+h];
        }
        g_W1c[idx]=acc1; g_W2c[idx]=acc2;
    }
}

// ---------------- K2: T5 relative-position buckets ----------------
__global__ void k_bucket(){
    int idx = blockIdx.x*blockDim.x + threadIdx.x;
    if (idx >= SEQ*SEQ) return;
    int q = idx >> 9, k = idx & (SEQ-1);
    int n = q - k;                       // n = -(k-q)
    int ret = (n < 0) ? 16 : 0;
    int na = n < 0 ? -n : n;
    int bkt;
    if (na < 8) bkt = na;
    else {
        int v = (int)(log((double)na / 8.0) / log(5.0) * 8.0);
        if (v > 7) v = 7;
        bkt = 8 + v;
    }
    g_bucket[idx] = (unsigned char)(ret + bkt);
}

// ---------------- K3: QKV projection (warp per token) ----------------
__global__ void __launch_bounds__(512) k_qkv(const float* __restrict__ x, const int* __restrict__ ts,
                      const float* __restrict__ Wq, const float* __restrict__ Wk,
                      const float* __restrict__ Wv){
    __shared__ float sx[16*EMB];
    int tid=threadIdx.x, w=tid>>5, lane=tid&31;
    int token0 = blockIdx.x*16;
    const float4* xg = (const float4*)(x + token0*EMB);
    float4* s4 = (float4*)sx;
    for (int i=tid;i<16*EMB/4;i+=512) s4[i]=xg[i];
    __syncthreads();
    int token = token0 + w;
    int t = ts[token];
    int o = lane*8;
    const float* wq = Wq + t*EMB*EMB + o;
    const float* wk = Wk + t*EMB*EMB + o;
    const float* wv = Wv + t*EMB*EMB + o;
    float aq0=0,aq1=0,aq2=0,aq3=0,aq4=0,aq5=0,aq6=0,aq7=0;
    float ak0=0,ak1=0,ak2=0,ak3=0,ak4=0,ak5=0,ak6=0,ak7=0;
    float av0=0,av1=0,av2=0,av3=0,av4=0,av5=0,av6=0,av7=0;
    const float* xr = sx + w*EMB;
    #pragma unroll 4
    for (int i=0;i<EMB;i++){
        float xi = xr[i];
        float4 a = *(const float4*)(wq + i*EMB);
        float4 b = *(const float4*)(wq + i*EMB + 4);
        aq0+=xi*a.x; aq1+=xi*a.y; aq2+=xi*a.z; aq3+=xi*a.w;
        aq4+=xi*b.x; aq5+=xi*b.y; aq6+=xi*b.z; aq7+=xi*b.w;
        float4 c = *(const float4*)(wk + i*EMB);
        float4 d = *(const float4*)(wk + i*EMB + 4);
        ak0+=xi*c.x; ak1+=xi*c.y; ak2+=xi*c.z; ak3+=xi*c.w;
        ak4+=xi*d.x; ak5+=xi*d.y; ak6+=xi*d.z; ak7+=xi*d.w;
        float4 e = *(const float4*)(wv + i*EMB);
        float4 f = *(const float4*)(wv + i*EMB + 4);
        av0+=xi*e.x; av1+=xi*e.y; av2+=xi*e.z; av3+=xi*e.w;
        av4+=xi*f.x; av5+=xi*f.y; av6+=xi*f.z; av7+=xi*f.w;
    }
    int bb = token>>9, l = token&(SEQ-1);
    int h = o>>5, dd = o&31;
    int base = ((bb*NH+h)*SEQ+l)*HD + dd;
    *(float4*)&g_q[base]   = make_float4(aq0,aq1,aq2,aq3);
    *(float4*)&g_q[base+4] = make_float4(aq4,aq5,aq6,aq7);
    *(float4*)&g_k[base]   = make_float4(ak0,ak1,ak2,ak3);
    *(float4*)&g_k[base+4] = make_float4(ak4,ak5,ak6,ak7);
    *(float4*)&g_v[base]   = make_float4(av0,av1,av2,av3);
    *(float4*)&g_v[base+4] = make_float4(av4,av5,av6,av7);
}

// ---------------- K4: qA / u 4-slice precompute ----------------
__global__ void __launch_bounds__(256) k_qau(const int* __restrict__ ts){
    int bh = blockIdx.x >> 2;
    int qt = blockIdx.x & 3;
    int b = bh >> 3, h = bh & 7;
    int lane32 = threadIdx.x & 31;     // n (qA) / m (u)
    int tki    = (threadIdx.x >> 5) & 3;
    int qo     = threadIdx.x >> 7;     // 0..1
    for (int qi = qo; qi < 128; qi += 2){
        int q = qt*128 + qi;
        int tok_t = ts[b*SEQ + q];
        // qA[b][h][q][tki][n] = sum_m q[m] * W1c[cmap(tok_t, tki)][h][m][n]
        {
            int c = cmap(tok_t, tki);
            const float* wb = g_W1c + (c*NH+h)*HD*HD + lane32;
            const float* qv = g_q + (bh*SEQ+q)*HD;
            float a0=0,a1=0,a2=0,a3=0;
            #pragma unroll
            for (int m=0;m<HD;m+=4){
                a0 += qv[m  ]*wb[(m  )*HD];
                a1 += qv[m+1]*wb[(m+1)*HD];
                a2 += qv[m+2]*wb[(m+2)*HD];
                a3 += qv[m+3]*wb[(m+3)*HD];
            }
            g_qA[((bh*SEQ+q)*4 + tki)*HD + lane32] = (a0+a1)+(a2+a3);
        }
        // u[b][h][k][tki(=tq)][m] = sum_n v[n] * W2c[cmap(tki, tok_t)][h][n][m]
        {
            int c = cmap(tki, tok_t);
            const float* wb = g_W2c + (c*NH+h)*HD*HD + lane32;
            const float* vv = g_v + (bh*SEQ+q)*HD;
            float a0=0,a1=0,a2=0,a3=0;
            #pragma unroll
            for (int n=0;n<HD;n+=4){
                a0 += vv[n  ]*wb[(n  )*HD];
                a1 += vv[n+1]*wb[(n+1)*HD];
                a2 += vv[n+2]*wb[(n+2)*HD];
                a3 += vv[n+3]*wb[(n+3)*HD];
            }
            g_u[((bh*SEQ+q)*4 + tki)*HD + lane32] = (a0+a1)+(a2+a3);
        }
    }
}

// ---------------- K5: scores = qA(tk)·k * scale + bias + mask ----------------
__global__ void __launch_bounds__(256) k_scores(const float* __restrict__ mask,
                                                const int* __restrict__ ts,
                                                const float* __restrict__ rp){
    int bh = blockIdx.y; int b = bh>>3, h = bh&7;
    int q0 = blockIdx.x * 32;
    __shared__ float s_qA[32*4*HD];     // 16 KB
    __shared__ float s_rp[NC*NBUCK];
    __shared__ int   s_tq[32];
    int tid = threadIdx.x;
    {
        const float4* src = (const float4*)(g_qA + (bh*SEQ+q0)*4*HD);
        float4* dst = (float4*)s_qA;
        for (int i=tid;i<32*4*HD/4;i+=256) dst[i]=src[i];
    }
    for (int i=tid;i<NC*NBUCK;i+=256) s_rp[i] = rp[i*NH + h];
    if (tid<32) s_tq[tid] = ts[b*SEQ + q0 + tid];
    __syncthreads();
    const float scale = 0.17677669529663687f; // 1/sqrt(32)
    for (int kk = tid; kk < SEQ; kk += 256){
        int tkk = ts[b*SEQ+kk];
        float kv[HD];
        const float4* kg = (const float4*)(g_k + (bh*SEQ+kk)*HD);
        #pragma unroll
        for (int j=0;j<8;j++){ float4 t4=kg[j]; kv[4*j]=t4.x; kv[4*j+1]=t4.y; kv[4*j+2]=t4.z; kv[4*j+3]=t4.w; }
        const float* mrow = mask + (size_t)b*SEQ*SEQ + kk;
        const unsigned char* brow = g_bucket + kk;
        float* orow = g_sc + ((size_t)(bh*SEQ+q0))*SEQ + kk;
        for (int qi=0; qi<32; qi++){
            const float* qa = s_qA + (qi*4 + tkk)*HD;
            float a0=0,a1=0,a2=0,a3=0;
            #pragma unroll
            for (int j=0;j<HD;j+=4){
                a0 += qa[j  ]*kv[j  ];
                a1 += qa[j+1]*kv[j+1];
                a2 += qa[j+2]*kv[j+2];
                a3 += qa[j+3]*kv[j+3];
            }
            int q = q0 + qi;
            int c = cmap(s_tq[qi], tkk);
            float bias = s_rp[c*NBUCK + brow[q*SEQ]];
            orow[(size_t)qi*SEQ] = ((a0+a1)+(a2+a3))*scale + bias + mrow[(size_t)q*SEQ];
        }
    }
}

// ---------------- K6: row softmax (in place) ----------------
__global__ void __launch_bounds__(256) k_softmax(){
    int row = blockIdx.x;
    float* p = g_sc + (size_t)row*SEQ;
    int tid = threadIdx.x;
    float v0 = p[tid], v1 = p[tid+256];
    float m = fmaxf(v0,v1);
    #pragma unroll
    for (int o=16;o;o>>=1) m = fmaxf(m, __shfl_xor_sync(0xffffffffu,m,o));
    __shared__ float sm[8];
    if ((tid&31)==0) sm[tid>>5]=m;
    __syncthreads();
    float mm = sm[0];
    #pragma unroll
    for (int i=1;i<8;i++) mm = fmaxf(mm, sm[i]);
    float e0 = __expf(v0-mm), e1 = __expf(v1-mm);
    float s = e0+e1;
    #pragma unroll
    for (int o=16;o;o>>=1) s += __shfl_xor_sync(0xffffffffu,s,o);
    __shared__ float ssum[8];
    if ((tid&31)==0) ssum[tid>>5]=s;
    __syncthreads();
    float tot = 0.f;
    #pragma unroll
    for (int i=0;i<8;i++) tot += ssum[i];
    float inv = 1.0f/tot;
    p[tid]     = e0*inv;
    p[tid+256] = e1*inv;
}

// ---------------- K7: ctx = probs @ u[:, tq(q), :] ----------------
__global__ void __launch_bounds__(256) k_ctx(const int* __restrict__ ts){
    int bh = blockIdx.y, b = bh>>3, h = bh&7;
    int q0 = blockIdx.x*32;
    __shared__ float s_p[32][65];     // padded
    __shared__ float s_u[64*4*HD];    // 32 KB
    __shared__ int   s_tq[32];
    int tid=threadIdx.x;
    if (tid<32) s_tq[tid]=ts[b*SEQ+q0+tid];
    int qi = tid>>3, g = tid&7;
    float ax=0,ay=0,az=0,aw=0;
    for (int kt=0; kt<8; kt++){
        __syncthreads();
        for (int i=tid;i<2048;i+=256){
            int qq=i>>6, kk=i&63;
            s_p[qq][kk] = g_sc[((size_t)(bh*SEQ+q0+qq))*SEQ + kt*64 + kk];
        }
        {
            const float4* src = (const float4*)(g_u + (size_t)(bh*SEQ + kt*64)*4*HD);
            float4* dst = (float4*)s_u;
            for (int i=tid;i<64*4*HD/4;i+=256) dst[i]=src[i];
        }
        __syncthreads();
        int tq = s_tq[qi];
        #pragma unroll 4
        for (int kk=0;kk<64;kk++){
            float pp = s_p[qi][kk];
            float4 uu = *(const float4*)(s_u + (kk*4+tq)*HD + g*4);
            ax += pp*uu.x; ay += pp*uu.y; az += pp*uu.z; aw += pp*uu.w;
        }
    }
    int q = q0+qi;
    *(float4*)&g_ctx[((size_t)(b*SEQ+q))*EMB + h*HD + g*4] = make_float4(ax,ay,az,aw);
}

// ---------------- K8: residual + LayerNorm ----------------
__global__ void __launch_bounds__(256) k_ln(const float* __restrict__ x,
                                            const float* __restrict__ gamma,
                                            const float* __restrict__ beta,
                                            float* __restrict__ out){
    int tok = blockIdx.x;
    int tid = threadIdx.x;
    float xv = g_ctx[(size_t)tok*EMB+tid] + x[(size_t)tok*EMB+tid];
    float s = xv;
    #pragma unroll
    for (int o=16;o;o>>=1) s += __shfl_xor_sync(0xffffffffu,s,o);
    __shared__ float r1[8];
    if ((tid&31)==0) r1[tid>>5]=s;
    __syncthreads();
    float tot=0.f;
    #pragma unroll
    for (int i=0;i<8;i++) tot += r1[i];
    float mu = tot*(1.0f/EMB);
    float d = xv - mu;
    float s2 = d*d;
    #pragma unroll
    for (int o=16;o;o>>=1) s2 += __shfl_xor_sync(0xffffffffu,s2,o);
    __shared__ float r2[8];
    if ((tid&31)==0) r2[tid>>5]=s2;
    __syncthreads();
    float tot2=0.f;
    #pragma unroll
    for (int i=0;i<8;i++) tot2 += r2[i];
    float var = tot2*(1.0f/EMB);
    out[(size_t)tok*EMB+tid] = d * rsqrtf(var + 1e-12f) * gamma[tid] + beta[tid];
}

// ---------------- launch ----------------
extern "C" void kernel_launch(void* const* d_in, const int* in_sizes, int n_in,
                              void* d_out, int out_size){
    const float* x    = (const float*)d_in[0];
    const float* mask = (const float*)d_in[1];
    const int*   ts   = (const int*)  d_in[2];
    const float* Wq   = (const float*)d_in[3];
    const float* Wk   = (const float*)d_in[4];
    const float* Wv   = (const float*)d_in[5];
    const float* W1   = (const float*)d_in[6];
    const float* a1   = (const float*)d_in[7];
    const float* W2   = (const float*)d_in[8];
    const float* a2   = (const float*)d_in[9];
    const float* rp   = (const float*)d_in[10];
    const float* gam  = (const float*)d_in[11];
    const float* bet  = (const float*)d_in[12];
    float* out = (float*)d_out;

    k_prep   <<<1, 256>>>(W1, a1, W2, a2);
    k_bucket <<<(SEQ*SEQ+255)/256, 256>>>();
    k_qkv    <<<BATCH*SEQ/16, 512>>>(x, ts, Wq, Wk, Wv);
    k_qau    <<<BATCH*NH*4, 256>>>(ts);
    k_scores <<<dim3(SEQ/32, BATCH*NH), 256>>>(mask, ts, rp);
    k_softmax<<<BATCH*NH*SEQ, 256>>>();
    k_ctx    <<<dim3(SEQ/32, BATCH*NH), 256>>>(ts);
    k_ln     <<<BATCH*SEQ, 256>>>(x, gam, bet, out);
}

// round 3
// speedup vs baseline: 1.5335x; 1.5316x over previous
#include <cuda_runtime.h>
#include <math.h>

#define BATCH 4
#define SEQ   512
#define EMB   256
#define NH    8
#define HD    32
#define NC    10
#define NBUCK 32

// ---------------- scratch ----------------
__device__ float g_W1c[NC*NH*HD*HD];
__device__ float g_W2c[NC*NH*HD*HD];
__device__ float g_q [BATCH*NH*SEQ*HD];       // sorted token order
__device__ float g_k [BATCH*NH*SEQ*HD];
__device__ float g_v [BATCH*NH*SEQ*HD];
__device__ float g_qA[BATCH*NH*SEQ*4*HD];     // [bh][pos][tk][n]  sorted
__device__ float g_u [BATCH*NH*SEQ*4*HD];     // [bh][pos][tq][m]  sorted
__device__ float g_sc[BATCH*NH*SEQ*SEQ];      // probs, sorted q & k
__device__ float g_ctx[BATCH*SEQ*EMB];        // ORIGINAL order
__device__ unsigned char g_bucket[SEQ*SEQ];
__device__ int g_perm [BATCH*SEQ];            // sorted pos -> orig idx
__device__ int g_stype[BATCH*SEQ];            // type at sorted pos
__device__ int g_base [BATCH*4];              // segment start per (b,type)

__device__ __forceinline__ int cmap(int tq, int tk){
    return (tq==0 || tk==0) ? 0 : (tq-1)*3 + tk;
}

// ---------------- K1: softmax(alpha) + combined W ----------------
__global__ void k_prep(const float* __restrict__ W1, const float* __restrict__ a1,
                       const float* __restrict__ W2, const float* __restrict__ a2){
    __shared__ float sa1[NC*3*NH];
    __shared__ float sa2[NC*3*NH];
    int tid = threadIdx.x;
    if (tid < NC*NH){
        int Ci = tid / NH, h = tid % NH;
        {
            float v0=a1[(Ci*3+0)*NH+h], v1=a1[(Ci*3+1)*NH+h], v2=a1[(Ci*3+2)*NH+h];
            float mx=fmaxf(v0,fmaxf(v1,v2));
            float e0=expf(v0-mx), e1=expf(v1-mx), e2=expf(v2-mx);
            float inv=1.0f/(e0+e1+e2);
            sa1[(Ci*3+0)*NH+h]=e0*inv; sa1[(Ci*3+1)*NH+h]=e1*inv; sa1[(Ci*3+2)*NH+h]=e2*inv;
        }
        {
            float v0=a2[(Ci*3+0)*NH+h], v1=a2[(Ci*3+1)*NH+h], v2=a2[(Ci*3+2)*NH+h];
            float mx=fmaxf(v0,fmaxf(v1,v2));
            float e0=expf(v0-mx), e1=expf(v1-mx), e2=expf(v2-mx);
            float inv=1.0f/(e0+e1+e2);
            sa2[(Ci*3+0)*NH+h]=e0*inv; sa2[(Ci*3+1)*NH+h]=e1*inv; sa2[(Ci*3+2)*NH+h]=e2*inv;
        }
    }
    __syncthreads();
    for (int idx=tid; idx<NC*NH*HD*HD; idx+=blockDim.x){
        int n = idx & 31, m = (idx>>5)&31, h=(idx>>10)&7, Ci = idx>>13;
        float acc1=0.f, acc2=0.f;
        #pragma unroll
        for (int b=0;b<3;b++){
            acc1 += W1[((b*NH+h)*HD+m)*HD+n] * sa1[(Ci*3+b)*NH+h];
            acc2 += W2[((b*NH+h)*HD+m)*HD+n] * sa2[(Ci*3+b)*NH+h];
        }
        g_W1c[idx]=acc1; g_W2c[idx]=acc2;
    }
}

// ---------------- K2: T5 buckets ----------------
__global__ void k_bucket(){
    int idx = blockIdx.x*blockDim.x + threadIdx.x;
    if (idx >= SEQ*SEQ) return;
    int q = idx >> 9, k = idx & (SEQ-1);
    int n = q - k;
    int ret = (n < 0) ? 16 : 0;
    int na = n < 0 ? -n : n;
    int bkt;
    if (na < 8) bkt = na;
    else {
        int v = (int)(log((double)na / 8.0) / log(5.0) * 8.0);
        if (v > 7) v = 7;
        bkt = 8 + v;
    }
    g_bucket[idx] = (unsigned char)(ret + bkt);
}

// ---------------- K3: stable counting sort by type (1 block / batch) ----------------
__global__ void __launch_bounds__(512) k_sort(const int* __restrict__ ts){
    int b = blockIdx.x;
    __shared__ int wcnt[4][16];
    __shared__ int wbase[4][16];
    __shared__ int sbase[4];
    int tid = threadIdx.x, w = tid>>5, lane = tid&31;
    int t = ts[b*SEQ + tid];
    unsigned b0 = __ballot_sync(0xffffffffu, t==0);
    unsigned b1 = __ballot_sync(0xffffffffu, t==1);
    unsigned b2 = __ballot_sync(0xffffffffu, t==2);
    unsigned b3 = __ballot_sync(0xffffffffu, t==3);
    if (lane==0){
        wcnt[0][w]=__popc(b0); wcnt[1][w]=__popc(b1);
        wcnt[2][w]=__popc(b2); wcnt[3][w]=__popc(b3);
    }
    __syncthreads();
    if (tid==0){
        int cum=0;
        for (int tt=0;tt<4;tt++){
            sbase[tt]=cum;
            for (int ww=0;ww<16;ww++){ wbase[tt][ww]=cum; cum+=wcnt[tt][ww]; }
        }
    }
    __syncthreads();
    unsigned mybal = (t==0)?b0:(t==1)?b1:(t==2)?b2:b3;
    int pos = wbase[t][w] + __popc(mybal & ((1u<<lane)-1u));
    g_perm [b*SEQ + pos] = tid;
    g_stype[b*SEQ + pos] = t;
    if (tid<4) g_base[b*4+tid] = sbase[tid];
}

// ---------------- K4: QKV as type-pure tiled GEMM ----------------
// grid: x=chunk(16), y=b*4+t(16), z=component(3). block 256.
__global__ void __launch_bounds__(256) k_qkv(const float* __restrict__ x, const float* __restrict__ Wq,
                                             const float* __restrict__ Wk, const float* __restrict__ Wv){
    int b = blockIdx.y >> 2, t = blockIdx.y & 3;
    int base = g_base[b*4+t];
    int end  = (t==3) ? SEQ : g_base[b*4+t+1];
    int tok0 = base + blockIdx.x*32;
    if (tok0 >= end) return;
    int ntok = end - tok0; if (ntok > 32) ntok = 32;

    const float* W = ((blockIdx.z==0)?Wq:(blockIdx.z==1)?Wk:Wv) + (size_t)t*EMB*EMB;
    float* gout = (blockIdx.z==0)?g_q:(blockIdx.z==1)?g_k:g_v;

    __shared__ float sx[32][32];    // [k][tok]
    __shared__ float sw[32*256];    // [k][col]
    __shared__ int   sorig[32];

    int tid = threadIdx.x;
    int tg = tid >> 5;      // token group (0..7) -> tokens tg*4..tg*4+3
    int c  = tid & 31;      // col group    -> cols c*8..c*8+7

    if (tid < 32) sorig[tid] = (tid < ntok) ? g_perm[b*SEQ + tok0 + tid] : 0;
    __syncthreads();

    float acc[4][8];
    #pragma unroll
    for (int i=0;i<4;i++)
        #pragma unroll
        for (int j=0;j<8;j++) acc[i][j]=0.f;

    for (int kt=0; kt<8; kt++){
        int k0 = kt*32;
        // load x tile (transposed into [k][tok])
        {
            int j   = tid >> 3;        // token 0..31
            int kk4 = (tid & 7) * 4;   // k offset
            float4 xv = make_float4(0.f,0.f,0.f,0.f);
            if (j < ntok)
                xv = *(const float4*)(x + ((size_t)(b*SEQ) + sorig[j])*EMB + k0 + kk4);
            sx[kk4+0][j]=xv.x; sx[kk4+1][j]=xv.y; sx[kk4+2][j]=xv.z; sx[kk4+3][j]=xv.w;
        }
        // load W tile [32k][256c]
        {
            const float4* wg = (const float4*)(W + (size_t)k0*EMB);
            float4* swd = (float4*)sw;
            #pragma unroll
            for (int s=0;s<8;s++) swd[s*256 + tid] = wg[s*256 + tid];
        }
        __syncthreads();
        #pragma unroll 4
        for (int k=0;k<32;k++){
            float4 xv = *(const float4*)&sx[k][tg*4];     // broadcast within warp
            float4 w0 = *(const float4*)&sw[k*256 + c*8];
            float4 w1 = *(const float4*)&sw[k*256 + c*8 + 4];
            acc[0][0]+=xv.x*w0.x; acc[0][1]+=xv.x*w0.y; acc[0][2]+=xv.x*w0.z; acc[0][3]+=xv.x*w0.w;
            acc[0][4]+=xv.x*w1.x; acc[0][5]+=xv.x*w1.y; acc[0][6]+=xv.x*w1.z; acc[0][7]+=xv.x*w1.w;
            acc[1][0]+=xv.y*w0.x; acc[1][1]+=xv.y*w0.y; acc[1][2]+=xv.y*w0.z; acc[1][3]+=xv.y*w0.w;
            acc[1][4]+=xv.y*w1.x; acc[1][5]+=xv.y*w1.y; acc[1][6]+=xv.y*w1.z; acc[1][7]+=xv.y*w1.w;
            acc[2][0]+=xv.z*w0.x; acc[2][1]+=xv.z*w0.y; acc[2][2]+=xv.z*w0.z; acc[2][3]+=xv.z*w0.w;
            acc[2][4]+=xv.z*w1.x; acc[2][5]+=xv.z*w1.y; acc[2][6]+=xv.z*w1.z; acc[2][7]+=xv.z*w1.w;
            acc[3][0]+=xv.w*w0.x; acc[3][1]+=xv.w*w0.y; acc[3][2]+=xv.w*w0.z; acc[3][3]+=xv.w*w0.w;
            acc[3][4]+=xv.w*w1.x; acc[3][5]+=xv.w*w1.y; acc[3][6]+=xv.w*w1.z; acc[3][7]+=xv.w*w1.w;
        }
        __syncthreads();
    }
    // write: [bh][pos][d]
    int h = (c*8) >> 5, d = (c*8) & 31;
    #pragma unroll
    for (int j=0;j<4;j++){
        int tokj = tg*4 + j;
        if (tokj < ntok){
            size_t o = ((size_t)((b*NH+h)*SEQ) + tok0 + tokj)*HD + d;
            *(float4*)&gout[o]   = make_float4(acc[j][0],acc[j][1],acc[j][2],acc[j][3]);
            *(float4*)&gout[o+4] = make_float4(acc[j][4],acc[j][5],acc[j][6],acc[j][7]);
        }
    }
}

// ---------------- K5: qA/u with register-resident W ----------------
// grid: x=chunk(8 of 64 pos), y=bh(32), z=type(4). block 256 = 8 warps.
__global__ void __launch_bounds__(256) k_qau(){
    int bh = blockIdx.y, b = bh>>3, h = bh&7;
    int t  = blockIdx.z;
    int base = g_base[b*4+t];
    int end  = (t==3) ? SEQ : g_base[b*4+t+1];
    int pos0 = base + blockIdx.x*64;
    if (pos0 >= end) return;
    int n = end - pos0; if (n > 64) n = 64;

    __shared__ float sq[64*HD];
    __shared__ float sv[64*HD];
    int tid = threadIdx.x, w = tid>>5, lane = tid&31;

    {   // stage q and v tiles (rows beyond n unused)
        const float4* qg = (const float4*)(g_q + (size_t)(bh*SEQ+pos0)*HD);
        const float4* vg = (const float4*)(g_v + (size_t)(bh*SEQ+pos0)*HD);
        float4* sq4 = (float4*)sq; float4* sv4 = (float4*)sv;
        int lim = n*HD/4;
        for (int i=tid;i<512;i+=256){
            sq4[i] = (i<lim) ? qg[i] : make_float4(0,0,0,0);
            sv4[i] = (i<lim) ? vg[i] : make_float4(0,0,0,0);
        }
    }
    // W column into registers
    float wr[32];
    bool isA = (w < 4);
    int slot = isA ? w : (w-4);            // tk for qA, tq for u
    int cc = isA ? cmap(t, slot) : cmap(slot, t);
    const float* wsrc = (isA ? g_W1c : g_W2c) + ((size_t)(cc*NH+h)*HD)*HD + lane;
    #pragma unroll
    for (int m=0;m<32;m++) wr[m] = wsrc[m*HD];
    __syncthreads();

    const float* tile = isA ? sq : sv;
    float* gdst = isA ? g_qA : g_u;
    for (int p=0;p<n;p++){
        const float* r = tile + p*HD;
        float a0=0,a1=0,a2=0,a3=0;
        #pragma unroll
        for (int m=0;m<32;m+=4){
            a0 += r[m  ]*wr[m  ];
            a1 += r[m+1]*wr[m+1];
            a2 += r[m+2]*wr[m+2];
            a3 += r[m+3]*wr[m+3];
        }
        gdst[((size_t)(bh*SEQ + pos0 + p)*4 + slot)*HD + lane] = (a0+a1)+(a2+a3);
    }
}

// ---------------- K6: scores + bias + mask + fused softmax ----------------
// grid: x = qtile(32 of 16 q), y = bh(32). block 256.
__global__ void __launch_bounds__(256) k_scores(const float* __restrict__ mask,
                                                const float* __restrict__ rp){
    int bh = blockIdx.y, b = bh>>3, h = bh&7;
    int q0 = blockIdx.x*16;
    __shared__ float s_sc[16][512];       // 32KB
    __shared__ float s_qA[16*4*HD];       // 8KB
    __shared__ float s_rp[NC*NBUCK];
    __shared__ int   s_origq[16], s_tq[16];
    int tid = threadIdx.x, w = tid>>5, lane = tid&31;
    {
        const float4* src = (const float4*)(g_qA + (size_t)(bh*SEQ+q0)*4*HD);
        float4* dst = (float4*)s_qA;
        for (int i=tid;i<16*4*HD/4;i+=256) dst[i]=src[i];
    }
    for (int i=tid;i<NC*NBUCK;i+=256) s_rp[i] = rp[i*NH + h];
    if (tid<16){ s_origq[tid]=g_perm[b*SEQ+q0+tid]; s_tq[tid]=g_stype[b*SEQ+q0+tid]; }
    __syncthreads();

    const float scale = 0.17677669529663687f;
    for (int chunk=w; chunk<16; chunk+=8){
        int kp = chunk*32 + lane;
        int tkk   = g_stype[b*SEQ + kp];
        int origk = g_perm [b*SEQ + kp];
        float kv[HD];
        const float4* kg = (const float4*)(g_k + (size_t)(bh*SEQ+kp)*HD);
        #pragma unroll
        for (int j=0;j<8;j++){ float4 t4=kg[j]; kv[4*j]=t4.x; kv[4*j+1]=t4.y; kv[4*j+2]=t4.z; kv[4*j+3]=t4.w; }
        const float* qab = s_qA + tkk*HD;
        const unsigned char* brow = g_bucket + origk;
        #pragma unroll 2
        for (int qi=0;qi<16;qi++){
            const float* qa = qab + qi*4*HD;
            float a0=0,a1=0,a2=0,a3=0;
            #pragma unroll
            for (int j=0;j<HD;j+=4){
                a0 += qa[j  ]*kv[j  ];
                a1 += qa[j+1]*kv[j+1];
                a2 += qa[j+2]*kv[j+2];
                a3 += qa[j+3]*kv[j+3];
            }
            int c = cmap(s_tq[qi], tkk);
            float bias = s_rp[c*NBUCK + brow[(size_t)s_origq[qi]*SEQ]];
            float mv = mask[((size_t)(b*SEQ)+s_origq[qi])*SEQ + origk];
            s_sc[qi][chunk*32+lane] = ((a0+a1)+(a2+a3))*scale + bias + mv;
        }
    }
    __syncthreads();
    // softmax: warp w handles rows 2w, 2w+1
    #pragma unroll
    for (int rr=0; rr<2; rr++){
        int r = w*2 + rr;
        float4 v[4];
        #pragma unroll
        for (int i=0;i<4;i++) v[i] = *(const float4*)&s_sc[r][lane*4 + i*128];
        float m = -1e30f;
        #pragma unroll
        for (int i=0;i<4;i++) m = fmaxf(m, fmaxf(fmaxf(v[i].x,v[i].y), fmaxf(v[i].z,v[i].w)));
        #pragma unroll
        for (int o=16;o;o>>=1) m = fmaxf(m, __shfl_xor_sync(0xffffffffu, m, o));
        float s = 0.f;
        #pragma unroll
        for (int i=0;i<4;i++){
            v[i].x=__expf(v[i].x-m); v[i].y=__expf(v[i].y-m);
            v[i].z=__expf(v[i].z-m); v[i].w=__expf(v[i].w-m);
            s += (v[i].x+v[i].y)+(v[i].z+v[i].w);
        }
        #pragma unroll
        for (int o=16;o;o>>=1) s += __shfl_xor_sync(0xffffffffu, s, o);
        float inv = 1.0f/s;
        float* orow = g_sc + (size_t)(bh*SEQ+q0+r)*SEQ;
        #pragma unroll
        for (int i=0;i<4;i++){
            *(float4*)&orow[lane*4 + i*128] =
                make_float4(v[i].x*inv, v[i].y*inv, v[i].z*inv, v[i].w*inv);
        }
    }
}

// ---------------- K7: ctx = probs @ u[:, tq, :], scatter to orig order ----------------
__global__ void __launch_bounds__(256) k_ctx(){
    int bh = blockIdx.y, b = bh>>3, h = bh&7;
    int q0 = blockIdx.x*32;
    __shared__ float s_p[32][65];
    __shared__ float s_u[64*4*HD];        // 32KB
    __shared__ int   s_tq[32], s_oq[32];
    int tid=threadIdx.x;
    if (tid<32){ s_tq[tid]=g_stype[b*SEQ+q0+tid]; s_oq[tid]=g_perm[b*SEQ+q0+tid]; }
    int qi = tid>>3, g = tid&7;
    float ax=0,ay=0,az=0,aw=0;
    for (int kt=0; kt<8; kt++){
        __syncthreads();
        for (int i=tid;i<2048;i+=256){
            int qq=i>>6, kk=i&63;
            s_p[qq][kk] = g_sc[((size_t)(bh*SEQ+q0+qq))*SEQ + kt*64 + kk];
        }
        {
            const float4* src = (const float4*)(g_u + (size_t)(bh*SEQ + kt*64)*4*HD);
            float4* dst = (float4*)s_u;
            for (int i=tid;i<64*4*HD/4;i+=256) dst[i]=src[i];
        }
        __syncthreads();
        int tq = s_tq[qi];
        #pragma unroll 4
        for (int kk=0;kk<64;kk++){
            float pp = s_p[qi][kk];
            float4 uu = *(const float4*)(s_u + (kk*4+tq)*HD + g*4);
            ax += pp*uu.x; ay += pp*uu.y; az += pp*uu.z; aw += pp*uu.w;
        }
    }
    int oq = s_oq[qi];
    *(float4*)&g_ctx[((size_t)(b*SEQ+oq))*EMB + h*HD + g*4] = make_float4(ax,ay,az,aw);
}

// ---------------- K8: residual + LayerNorm ----------------
__global__ void __launch_bounds__(256) k_ln(const float* __restrict__ x,
                                            const float* __restrict__ gamma,
                                            const float* __restrict__ beta,
                                            float* __restrict__ out){
    int tok = blockIdx.x;
    int tid = threadIdx.x;
    float xv = g_ctx[(size_t)tok*EMB+tid] + x[(size_t)tok*EMB+tid];
    float s = xv;
    #pragma unroll
    for (int o=16;o;o>>=1) s += __shfl_xor_sync(0xffffffffu,s,o);
    __shared__ float r1[8];
    if ((tid&31)==0) r1[tid>>5]=s;
    __syncthreads();
    float tot=0.f;
    #pragma unroll
    for (int i=0;i<8;i++) tot += r1[i];
    float mu = tot*(1.0f/EMB);
    float d = xv - mu;
    float s2 = d*d;
    #pragma unroll
    for (int o=16;o;o>>=1) s2 += __shfl_xor_sync(0xffffffffu,s2,o);
    __shared__ float r2[8];
    if ((tid&31)==0) r2[tid>>5]=s2;
    __syncthreads();
    float tot2=0.f;
    #pragma unroll
    for (int i=0;i<8;i++) tot2 += r2[i];
    float var = tot2*(1.0f/EMB);
    out[(size_t)tok*EMB+tid] = d * rsqrtf(var + 1e-12f) * gamma[tid] + beta[tid];
}

// ---------------- launch ----------------
extern "C" void kernel_launch(void* const* d_in, const int* in_sizes, int n_in,
                              void* d_out, int out_size){
    const float* x    = (const float*)d_in[0];
    const float* mask = (const float*)d_in[1];
    const int*   ts   = (const int*)  d_in[2];
    const float* Wq   = (const float*)d_in[3];
    const float* Wk   = (const float*)d_in[4];
    const float* Wv   = (const float*)d_in[5];
    const float* W1   = (const float*)d_in[6];
    const float* a1   = (const float*)d_in[7];
    const float* W2   = (const float*)d_in[8];
    const float* a2   = (const float*)d_in[9];
    const float* rp   = (const float*)d_in[10];
    const float* gam  = (const float*)d_in[11];
    const float* bet  = (const float*)d_in[12];
    float* out = (float*)d_out;

    k_prep  <<<1, 256>>>(W1, a1, W2, a2);
    k_bucket<<<(SEQ*SEQ+255)/256, 256>>>();
    k_sort  <<<BATCH, 512>>>(ts);
    k_qkv   <<<dim3(16, 16, 3), 256>>>(x, Wq, Wk, Wv);
    k_qau   <<<dim3(8, BATCH*NH, 4), 256>>>();
    k_scores<<<dim3(SEQ/16, BATCH*NH), 256>>>(mask, rp);
    k_ctx   <<<dim3(SEQ/32, BATCH*NH), 256>>>();
    k_ln    <<<BATCH*SEQ, 256>>>(x, gam, bet, out);
}

// round 4
// speedup vs baseline: 1.8472x; 1.2045x over previous
#include <cuda_runtime.h>
#include <math.h>

#define BATCH 4
#define SEQ   512
#define EMB   256
#define NH    8
#define HD    32
#define NC    10
#define NBUCK 32

// ---------------- scratch ----------------
__device__ float g_W1c[NC*NH*HD*HD];
__device__ float g_W2c[NC*NH*HD*HD];
__device__ float g_q [BATCH*NH*SEQ*HD];       // sorted token order
__device__ float g_k [BATCH*NH*SEQ*HD];
__device__ float g_v [BATCH*NH*SEQ*HD];
__device__ float g_qA[BATCH*NH*SEQ*4*HD];     // [bh][pos][tk][n]  sorted
__device__ float g_u [BATCH*NH*SEQ*4*HD];     // [bh][pos][tq][m]  sorted
__device__ float g_sc[BATCH*NH*SEQ*SEQ];      // probs, sorted q & k
__device__ float g_ctx[BATCH*SEQ*EMB];        // ORIGINAL order
__device__ unsigned char g_bucket[SEQ*SEQ];
__device__ int g_perm [BATCH*SEQ];
__device__ int g_stype[BATCH*SEQ];
__device__ int g_base [BATCH*4];
__device__ unsigned short g_code [BATCH*SEQ*SEQ];  // cmap*32+bucket, sorted coords
__device__ float          g_masks[BATCH*SEQ*SEQ];  // mask permuted to sorted coords

__device__ __forceinline__ int cmap(int tq, int tk){
    return (tq==0 || tk==0) ? 0 : (tq-1)*3 + tk;
}

// ---------------- K1: softmax(alpha) + combined W ----------------
__global__ void k_prep(const float* __restrict__ W1, const float* __restrict__ a1,
                       const float* __restrict__ W2, const float* __restrict__ a2){
    __shared__ float sa1[NC*3*NH];
    __shared__ float sa2[NC*3*NH];
    int tid = threadIdx.x;
    if (tid < NC*NH){
        int Ci = tid / NH, h = tid % NH;
        {
            float v0=a1[(Ci*3+0)*NH+h], v1=a1[(Ci*3+1)*NH+h], v2=a1[(Ci*3+2)*NH+h];
            float mx=fmaxf(v0,fmaxf(v1,v2));
            float e0=expf(v0-mx), e1=expf(v1-mx), e2=expf(v2-mx);
            float inv=1.0f/(e0+e1+e2);
            sa1[(Ci*3+0)*NH+h]=e0*inv; sa1[(Ci*3+1)*NH+h]=e1*inv; sa1[(Ci*3+2)*NH+h]=e2*inv;
        }
        {
            float v0=a2[(Ci*3+0)*NH+h], v1=a2[(Ci*3+1)*NH+h], v2=a2[(Ci*3+2)*NH+h];
            float mx=fmaxf(v0,fmaxf(v1,v2));
            float e0=expf(v0-mx), e1=expf(v1-mx), e2=expf(v2-mx);
            float inv=1.0f/(e0+e1+e2);
            sa2[(Ci*3+0)*NH+h]=e0*inv; sa2[(Ci*3+1)*NH+h]=e1*inv; sa2[(Ci*3+2)*NH+h]=e2*inv;
        }
    }
    __syncthreads();
    for (int idx=tid; idx<NC*NH*HD*HD; idx+=blockDim.x){
        int n = idx & 31, m = (idx>>5)&31, h=(idx>>10)&7, Ci = idx>>13;
        float acc1=0.f, acc2=0.f;
        #pragma unroll
        for (int b=0;b<3;b++){
            acc1 += W1[((b*NH+h)*HD+m)*HD+n] * sa1[(Ci*3+b)*NH+h];
            acc2 += W2[((b*NH+h)*HD+m)*HD+n] * sa2[(Ci*3+b)*NH+h];
        }
        g_W1c[idx]=acc1; g_W2c[idx]=acc2;
    }
}

// ---------------- K2: T5 buckets ----------------
__global__ void k_bucket(){
    int idx = blockIdx.x*blockDim.x + threadIdx.x;
    if (idx >= SEQ*SEQ) return;
    int q = idx >> 9, k = idx & (SEQ-1);
    int n = q - k;
    int ret = (n < 0) ? 16 : 0;
    int na = n < 0 ? -n : n;
    int bkt;
    if (na < 8) bkt = na;
    else {
        int v = (int)(log((double)na / 8.0) / log(5.0) * 8.0);
        if (v > 7) v = 7;
        bkt = 8 + v;
    }
    g_bucket[idx] = (unsigned char)(ret + bkt);
}

// ---------------- K3: stable counting sort by type ----------------
__global__ void __launch_bounds__(512) k_sort(const int* __restrict__ ts){
    int b = blockIdx.x;
    __shared__ int wcnt[4][16];
    __shared__ int wbase[4][16];
    __shared__ int sbase[4];
    int tid = threadIdx.x, w = tid>>5, lane = tid&31;
    int t = ts[b*SEQ + tid];
    unsigned b0 = __ballot_sync(0xffffffffu, t==0);
    unsigned b1 = __ballot_sync(0xffffffffu, t==1);
    unsigned b2 = __ballot_sync(0xffffffffu, t==2);
    unsigned b3 = __ballot_sync(0xffffffffu, t==3);
    if (lane==0){
        wcnt[0][w]=__popc(b0); wcnt[1][w]=__popc(b1);
        wcnt[2][w]=__popc(b2); wcnt[3][w]=__popc(b3);
    }
    __syncthreads();
    if (tid==0){
        int cum=0;
        for (int tt=0;tt<4;tt++){
            sbase[tt]=cum;
            for (int ww=0;ww<16;ww++){ wbase[tt][ww]=cum; cum+=wcnt[tt][ww]; }
        }
    }
    __syncthreads();
    unsigned mybal = (t==0)?b0:(t==1)?b1:(t==2)?b2:b3;
    int pos = wbase[t][w] + __popc(mybal & ((1u<<lane)-1u));
    g_perm [b*SEQ + pos] = tid;
    g_stype[b*SEQ + pos] = t;
    if (tid<4) g_base[b*4+tid] = sbase[tid];
}

// ---------------- K3b: permute mask + build code table (sorted coords) ----------------
__global__ void __launch_bounds__(256) k_gather(const float* __restrict__ mask){
    int b = blockIdx.y, qs = blockIdx.x;
    int origq = g_perm [b*SEQ+qs];
    int tq    = g_stype[b*SEQ+qs];
    const unsigned char* brow = g_bucket + (size_t)origq*SEQ;
    const float* mrow = mask + ((size_t)(b*SEQ)+origq)*SEQ;
    size_t obase = ((size_t)(b*SEQ)+qs)*SEQ;
    int tid = threadIdx.x;
    #pragma unroll
    for (int j=0;j<2;j++){
        int ks = tid + j*256;
        int origk = g_perm [b*SEQ+ks];
        int tk    = g_stype[b*SEQ+ks];
        int c = cmap(tq, tk);
        g_code [obase+ks] = (unsigned short)(c*NBUCK + brow[origk]);
        g_masks[obase+ks] = mrow[origk];
    }
}

// ---------------- K4: QKV as type-pure tiled SGEMM, 64x64 tile, 4x4 micro ----------------
// grid: x=m-chunk(8 of 64 tok), y=b*4+t(16), z=0..11 (comp*4 + n-tile). block 256.
__global__ void __launch_bounds__(256) k_qkv(const float* __restrict__ x, const float* __restrict__ Wq,
                                             const float* __restrict__ Wk, const float* __restrict__ Wv){
    int b = blockIdx.y >> 2, t = blockIdx.y & 3;
    int base = g_base[b*4+t];
    int end  = (t==3) ? SEQ : g_base[b*4+t+1];
    int m0 = base + blockIdx.x*64;
    if (m0 >= end) return;
    int mtok = end - m0; if (mtok > 64) mtok = 64;

    int comp = blockIdx.z >> 2;
    int n0   = (blockIdx.z & 3) * 64;
    const float* W = ((comp==0)?Wq:(comp==1)?Wk:Wv) + (size_t)t*EMB*EMB + n0;
    float* gout = (comp==0)?g_q:(comp==1)?g_k:g_v;

    __shared__ float sx[16][68];    // [k][m]
    __shared__ float sw[16][64];    // [k][n]
    __shared__ int   sorig[64];

    int tid = threadIdx.x;
    int ty = tid >> 4;   // 0..15 -> 4 token rows
    int tx = tid & 15;   // 0..15 -> 4 cols

    if (tid < 64) sorig[tid] = (tid < mtok) ? g_perm[b*SEQ + m0 + tid] : 0;
    __syncthreads();

    float acc[4][4];
    #pragma unroll
    for (int i=0;i<4;i++)
        #pragma unroll
        for (int j=0;j<4;j++) acc[i][j]=0.f;

    int xm  = tid >> 2;          // 0..63
    int xk4 = (tid & 3) * 4;     // 0,4,8,12
    const float* xrow = x + ((size_t)(b*SEQ) + sorig[xm])*EMB + xk4;
    int wk = tid >> 4;           // 0..15
    int wf = (tid & 15) * 4;     // 0..60

    for (int kt=0; kt<16; kt++){
        int k0 = kt*16;
        float4 xv = (xm < mtok) ? *(const float4*)(xrow + k0) : make_float4(0,0,0,0);
        float4 wv = *(const float4*)(W + (size_t)(k0+wk)*EMB + wf);
        __syncthreads();
        sx[xk4+0][xm]=xv.x; sx[xk4+1][xm]=xv.y; sx[xk4+2][xm]=xv.z; sx[xk4+3][xm]=xv.w;
        *(float4*)&sw[wk][wf] = wv;
        __syncthreads();
        #pragma unroll
        for (int k=0;k<16;k++){
            float4 a = *(const float4*)&sx[k][ty*4];
            float4 w4 = *(const float4*)&sw[k][tx*4];
            acc[0][0]+=a.x*w4.x; acc[0][1]+=a.x*w4.y; acc[0][2]+=a.x*w4.z; acc[0][3]+=a.x*w4.w;
            acc[1][0]+=a.y*w4.x; acc[1][1]+=a.y*w4.y; acc[1][2]+=a.y*w4.z; acc[1][3]+=a.y*w4.w;
            acc[2][0]+=a.z*w4.x; acc[2][1]+=a.z*w4.y; acc[2][2]+=a.z*w4.z; acc[2][3]+=a.z*w4.w;
            acc[3][0]+=a.w*w4.x; acc[3][1]+=a.w*w4.y; acc[3][2]+=a.w*w4.z; acc[3][3]+=a.w*w4.w;
        }
    }
    int ncol = n0 + tx*4;
    int h = ncol >> 5, d = ncol & 31;
    #pragma unroll
    for (int i=0;i<4;i++){
        int row = ty*4 + i;
        if (row < mtok){
            size_t o = ((size_t)((b*NH+h)*SEQ) + m0 + row)*HD + d;
            *(float4*)&gout[o] = make_float4(acc[i][0],acc[i][1],acc[i][2],acc[i][3]);
        }
    }
}

// ---------------- K5: qA/u with register-resident W ----------------
__global__ void __launch_bounds__(256) k_qau(){
    int bh = blockIdx.y, b = bh>>3, h = bh&7;
    int t  = blockIdx.z;
    int base = g_base[b*4+t];
    int end  = (t==3) ? SEQ : g_base[b*4+t+1];
    int pos0 = base + blockIdx.x*64;
    if (pos0 >= end) return;
    int n = end - pos0; if (n > 64) n = 64;

    __shared__ float sq[64*HD];
    __shared__ float sv[64*HD];
    int tid = threadIdx.x, w = tid>>5, lane = tid&31;

    {
        const float4* qg = (const float4*)(g_q + (size_t)(bh*SEQ+pos0)*HD);
        const float4* vg = (const float4*)(g_v + (size_t)(bh*SEQ+pos0)*HD);
        float4* sq4 = (float4*)sq; float4* sv4 = (float4*)sv;
        int lim = n*HD/4;
        for (int i=tid;i<512;i+=256){
            sq4[i] = (i<lim) ? qg[i] : make_float4(0,0,0,0);
            sv4[i] = (i<lim) ? vg[i] : make_float4(0,0,0,0);
        }
    }
    float wr[32];
    bool isA = (w < 4);
    int slot = isA ? w : (w-4);
    int cc = isA ? cmap(t, slot) : cmap(slot, t);
    const float* wsrc = (isA ? g_W1c : g_W2c) + ((size_t)(cc*NH+h)*HD)*HD + lane;
    #pragma unroll
    for (int m=0;m<32;m++) wr[m] = wsrc[m*HD];
    __syncthreads();

    const float* tile = isA ? sq : sv;
    float* gdst = isA ? g_qA : g_u;
    for (int p=0;p<n;p++){
        const float* r = tile + p*HD;
        float a0=0,a1=0,a2=0,a3=0;
        #pragma unroll
        for (int m=0;m<32;m+=4){
            a0 += r[m  ]*wr[m  ];
            a1 += r[m+1]*wr[m+1];
            a2 += r[m+2]*wr[m+2];
            a3 += r[m+3]*wr[m+3];
        }
        gdst[((size_t)(bh*SEQ + pos0 + p)*4 + slot)*HD + lane] = (a0+a1)+(a2+a3);
    }
}

// ---------------- K6: scores + bias + mask + fused softmax ----------------
__global__ void __launch_bounds__(256) k_scores(const float* __restrict__ rp){
    int bh = blockIdx.y, b = bh>>3, h = bh&7;
    int q0 = blockIdx.x*16;
    __shared__ float s_sc[16][512];
    __shared__ float s_qA[16*4*HD];
    __shared__ float s_rp[NC*NBUCK];
    int tid = threadIdx.x, w = tid>>5, lane = tid&31;
    {
        const float4* src = (const float4*)(g_qA + (size_t)(bh*SEQ+q0)*4*HD);
        float4* dst = (float4*)s_qA;
        for (int i=tid;i<16*4*HD/4;i+=256) dst[i]=src[i];
    }
    for (int i=tid;i<NC*NBUCK;i+=256) s_rp[i] = rp[i*NH + h];
    __syncthreads();

    const float scale = 0.17677669529663687f;
    #pragma unroll
    for (int cc=0; cc<2; cc++){
        int chunk = w + cc*8;
        int kp = chunk*32 + lane;
        int tkk = g_stype[b*SEQ + kp];
        float kv[HD];
        const float4* kg = (const float4*)(g_k + (size_t)(bh*SEQ+kp)*HD);
        #pragma unroll
        for (int j=0;j<8;j++){ float4 t4=kg[j]; kv[4*j]=t4.x; kv[4*j+1]=t4.y; kv[4*j+2]=t4.z; kv[4*j+3]=t4.w; }
        const unsigned short* crow = g_code  + ((size_t)(b*SEQ+q0))*SEQ + kp;
        const float*          mrow = g_masks + ((size_t)(b*SEQ+q0))*SEQ + kp;
        const float* qab = s_qA + tkk*HD;
        #pragma unroll 2
        for (int qi=0;qi<16;qi++){
            const float* qa = qab + qi*4*HD;
            float a0=0,a1=0,a2=0,a3=0;
            #pragma unroll
            for (int j=0;j<HD;j+=4){
                a0 += qa[j  ]*kv[j  ];
                a1 += qa[j+1]*kv[j+1];
                a2 += qa[j+2]*kv[j+2];
                a3 += qa[j+3]*kv[j+3];
            }
            float bias = s_rp[crow[(size_t)qi*SEQ]];
            float mv   = mrow[(size_t)qi*SEQ];
            s_sc[qi][chunk*32+lane] = ((a0+a1)+(a2+a3))*scale + bias + mv;
        }
    }
    __syncthreads();
    #pragma unroll
    for (int rr=0; rr<2; rr++){
        int r = w*2 + rr;
        float4 v[4];
        #pragma unroll
        for (int i=0;i<4;i++) v[i] = *(const float4*)&s_sc[r][lane*4 + i*128];
        float m = -1e30f;
        #pragma unroll
        for (int i=0;i<4;i++) m = fmaxf(m, fmaxf(fmaxf(v[i].x,v[i].y), fmaxf(v[i].z,v[i].w)));
        #pragma unroll
        for (int o=16;o;o>>=1) m = fmaxf(m, __shfl_xor_sync(0xffffffffu, m, o));
        float s = 0.f;
        #pragma unroll
        for (int i=0;i<4;i++){
            v[i].x=__expf(v[i].x-m); v[i].y=__expf(v[i].y-m);
            v[i].z=__expf(v[i].z-m); v[i].w=__expf(v[i].w-m);
            s += (v[i].x+v[i].y)+(v[i].z+v[i].w);
        }
        #pragma unroll
        for (int o=16;o;o>>=1) s += __shfl_xor_sync(0xffffffffu, s, o);
        float inv = 1.0f/s;
        float* orow = g_sc + (size_t)(bh*SEQ+q0+r)*SEQ;
        #pragma unroll
        for (int i=0;i<4;i++){
            *(float4*)&orow[lane*4 + i*128] =
                make_float4(v[i].x*inv, v[i].y*inv, v[i].z*inv, v[i].w*inv);
        }
    }
}

// ---------------- K7: ctx = probs @ u[:, tq, :], 64q x 32m tile, 4x4 micro ----------------
__global__ void __launch_bounds__(128) k_ctx(){
    int bh = blockIdx.y, b = bh>>3, h = bh&7;
    int q0 = blockIdx.x*64;
    __shared__ float s_p[64][68];
    __shared__ float s_uu[64*132];
    __shared__ int   s_tq[64], s_oq[64];
    int tid = threadIdx.x;
    if (tid < 64){ s_tq[tid]=g_stype[b*SEQ+q0+tid]; s_oq[tid]=g_perm[b*SEQ+q0+tid]; }
    __syncthreads();
    bool fast = (s_tq[0] == s_tq[63]);      // types sorted -> uniform iff ends match
    int t0 = s_tq[0];
    int qg = tid>>3, mg = tid&7;
    float acc[4][4];
    #pragma unroll
    for (int i=0;i<4;i++)
        #pragma unroll
        for (int j=0;j<4;j++) acc[i][j]=0.f;

    for (int kt=0; kt<8; kt++){
        __syncthreads();
        {
            const float* src = g_sc + ((size_t)(bh*SEQ+q0))*SEQ + kt*64;
            for (int idx=tid; idx<1024; idx+=128){
                int q = idx>>4, c4 = (idx&15)*4;
                *(float4*)&s_p[q][c4] = *(const float4*)(src + (size_t)q*SEQ + c4);
            }
        }
        if (fast){
            const float* ub = g_u + ((size_t)(bh*SEQ + kt*64))*4*HD + t0*HD;
            for (int idx=tid; idx<512; idx+=128){
                int kk = idx>>3, m4 = (idx&7)*4;
                *(float4*)&s_uu[kk*36 + m4] = *(const float4*)(ub + (size_t)kk*4*HD + m4);
            }
        } else {
            const float* ub = g_u + ((size_t)(bh*SEQ + kt*64))*4*HD;
            for (int idx=tid; idx<2048; idx+=128){
                int kk = idx>>5, p4 = (idx&31)*4;
                *(float4*)&s_uu[kk*132 + p4] = *(const float4*)(ub + (size_t)kk*4*HD + p4);
            }
        }
        __syncthreads();
        if (fast){
            #pragma unroll 4
            for (int k4=0;k4<64;k4+=4){
                float4 u0 = *(const float4*)&s_uu[(k4+0)*36 + mg*4];
                float4 u1 = *(const float4*)&s_uu[(k4+1)*36 + mg*4];
                float4 u2 = *(const float4*)&s_uu[(k4+2)*36 + mg*4];
                float4 u3 = *(const float4*)&s_uu[(k4+3)*36 + mg*4];
                #pragma unroll
                for (int i=0;i<4;i++){
                    float4 p = *(const float4*)&s_p[qg*4+i][k4];
                    acc[i][0] += p.x*u0.x + p.y*u1.x + p.z*u2.x + p.w*u3.x;
                    acc[i][1] += p.x*u0.y + p.y*u1.y + p.z*u2.y + p.w*u3.y;
                    acc[i][2] += p.x*u0.z + p.y*u1.z + p.z*u2.z + p.w*u3.z;
                    acc[i][3] += p.x*u0.w + p.y*u1.w + p.z*u2.w + p.w*u3.w;
                }
            }
        } else {
            #pragma unroll 2
            for (int k4=0;k4<64;k4+=4){
                #pragma unroll
                for (int i=0;i<4;i++){
                    int tq = s_tq[qg*4+i];
                    int ubase = tq*HD + mg*4;
                    float4 u0 = *(const float4*)&s_uu[(k4+0)*132 + ubase];
                    float4 u1 = *(const float4*)&s_uu[(k4+1)*132 + ubase];
                    float4 u2 = *(const float4*)&s_uu[(k4+2)*132 + ubase];
                    float4 u3 = *(const float4*)&s_uu[(k4+3)*132 + ubase];
                    float4 p = *(const float4*)&s_p[qg*4+i][k4];
                    acc[i][0] += p.x*u0.x + p.y*u1.x + p.z*u2.x + p.w*u3.x;
                    acc[i][1] += p.x*u0.y + p.y*u1.y + p.z*u2.y + p.w*u3.y;
                    acc[i][2] += p.x*u0.z + p.y*u1.z + p.z*u2.z + p.w*u3.z;
                    acc[i][3] += p.x*u0.w + p.y*u1.w + p.z*u2.w + p.w*u3.w;
                }
            }
        }
    }
    #pragma unroll
    for (int i=0;i<4;i++){
        int oq = s_oq[qg*4+i];
        *(float4*)&g_ctx[((size_t)(b*SEQ+oq))*EMB + h*HD + mg*4] =
            make_float4(acc[i][0],acc[i][1],acc[i][2],acc[i][3]);
    }
}

// ---------------- K8: residual + LayerNorm ----------------
__global__ void __launch_bounds__(256) k_ln(const float* __restrict__ x,
                                            const float* __restrict__ gamma,
                                            const float* __restrict__ beta,
                                            float* __restrict__ out){
    int tok = blockIdx.x;
    int tid = threadIdx.x;
    float xv = g_ctx[(size_t)tok*EMB+tid] + x[(size_t)tok*EMB+tid];
    float s = xv;
    #pragma unroll
    for (int o=16;o;o>>=1) s += __shfl_xor_sync(0xffffffffu,s,o);
    __shared__ float r1[8];
    if ((tid&31)==0) r1[tid>>5]=s;
    __syncthreads();
    float tot=0.f;
    #pragma unroll
    for (int i=0;i<8;i++) tot += r1[i];
    float mu = tot*(1.0f/EMB);
    float d = xv - mu;
    float s2 = d*d;
    #pragma unroll
    for (int o=16;o;o>>=1) s2 += __shfl_xor_sync(0xffffffffu,s2,o);
    __shared__ float r2[8];
    if ((tid&31)==0) r2[tid>>5]=s2;
    __syncthreads();
    float tot2=0.f;
    #pragma unroll
    for (int i=0;i<8;i++) tot2 += r2[i];
    float var = tot2*(1.0f/EMB);
    out[(size_t)tok*EMB+tid] = d * rsqrtf(var + 1e-12f) * gamma[tid] + beta[tid];
}

// ---------------- launch ----------------
extern "C" void kernel_launch(void* const* d_in, const int* in_sizes, int n_in,
                              void* d_out, int out_size){
    const float* x    = (const float*)d_in[0];
    const float* mask = (const float*)d_in[1];
    const int*   ts   = (const int*)  d_in[2];
    const float* Wq   = (const float*)d_in[3];
    const float* Wk   = (const float*)d_in[4];
    const float* Wv   = (const float*)d_in[5];
    const float* W1   = (const float*)d_in[6];
    const float* a1   = (const float*)d_in[7];
    const float* W2   = (const float*)d_in[8];
    const float* a2   = (const float*)d_in[9];
    const float* rp   = (const float*)d_in[10];
    const float* gam  = (const float*)d_in[11];
    const float* bet  = (const float*)d_in[12];
    float* out = (float*)d_out;

    k_prep  <<<1, 256>>>(W1, a1, W2, a2);
    k_bucket<<<(SEQ*SEQ+255)/256, 256>>>();
    k_sort  <<<BATCH, 512>>>(ts);
    k_gather<<<dim3(SEQ, BATCH), 256>>>(mask);
    k_qkv   <<<dim3(8, 16, 12), 256>>>(x, Wq, Wk, Wv);
    k_qau   <<<dim3(8, BATCH*NH, 4), 256>>>();
    k_scores<<<dim3(SEQ/16, BATCH*NH), 256>>>(rp);
    k_ctx   <<<dim3(SEQ/64, BATCH*NH), 128>>>();
    k_ln    <<<BATCH*SEQ, 256>>>(x, gam, bet, out);
}